// round 15
// baseline (speedup 1.0000x reference)
#include <cuda_runtime.h>
#include <cuda_fp16.h>

#define Nn   100000
#define Ee   1600000
#define HIDD 128
#define HEADS 4
#define CH   32
#define LL   2
#define GG   64
#define NCHUNK ((Nn + 255) / 256)   // 391

// ---------------- scratch (static device globals; no allocation) -----------
__device__ __align__(16) __half   g_hh[Nn*HIDD];    // h (fp16, sole copy)
__device__ __align__(16) __half   g_xsh[Nn*HIDD];   // fp16 xs (consumer: k_edge)
__device__ __align__(16) float    g_as[Nn*HEADS];
__device__ __align__(16) float    g_ad[Nn*HEADS];
__device__ __align__(16) float    g_uv[2*LL*HEADS];
__device__ __align__(16) float    g_pooled[GG*HIDD];
__device__           float        g_cnt[GG];
__device__ __align__(16) unsigned g_wt[2*2*64*64];  // W fp16, transposed+swizzled
// CSR by destination
__device__ __align__(16) int      g_deg[Nn];
__device__ __align__(16) int      g_row[Nn + 1];
__device__ __align__(16) int      g_cur[Nn];
__device__ __align__(16) int      g_bsum[NCHUNK];
__device__ __align__(16) int      g_boff[NCHUNK];
__device__ __align__(16) int2     g_pack[Ee];      // (src, ea bits)

__device__ __forceinline__ unsigned smem_u32(const void* p) {
    unsigned a;
    asm("{ .reg .u64 t; cvta.to.shared.u64 t, %1; cvt.u32.u64 %0, t; }"
        : "=r"(a) : "l"(p));
    return a;
}

// ---- block 0: uv precompute; blocks 1-4: W fp16 transpose; all: zero deg --
__global__ void k_uv(const float* __restrict__ eenc_w, const float* __restrict__ eenc_b,
                     const float* __restrict__ lew, const float* __restrict__ att_e,
                     const float* __restrict__ lin_w) {
    int i = blockIdx.x * blockDim.x + threadIdx.x;
    if (i < Nn) g_deg[i] = 0;
    if (blockIdx.x >= 1 && blockIdx.x <= 4) {
        int li = (blockIdx.x - 1) >> 1, yy = (blockIdx.x - 1) & 1;
        const float* W = lin_w + li * HIDD * HIDD;
#pragma unroll
        for (int q = 0; q < 16; q++) {
            int idx = threadIdx.x + q * 256;   // 0..4095
            int hk = idx >> 6, col = idx & 63;
            float w0 = W[(2 * hk) * HIDD + yy * 64 + col];
            float w1 = W[(2 * hk + 1) * HIDD + yy * 64 + col];
            __half2 v = __floats2half2_rn(w0, w1);
            g_wt[((li * 2 + yy) * 64 + col) * 64 + (hk ^ ((col & 7) << 2))] =
                *(unsigned*)&v;
        }
        return;
    }
    if (blockIdx.x != 0) return;
    int tid = threadIdx.x;                 // 256 = L*H*C
    int l = tid >> 7, h = (tid >> 5) & 3, c = tid & 31;
    const float* W = lew + l * HIDD * HIDD;
    int col = h * CH + c;
    float wc = 0.f, bc = 0.f;
    for (int k = 0; k < HIDD; k++) {
        float w = W[k * HIDD + col];
        wc += eenc_w[k] * w;
        bc += eenc_b[k] * w;
    }
    float ae = att_e[l * HEADS * CH + h * CH + c];
    float uu = wc * ae, vv = bc * ae;
    for (int off = 16; off; off >>= 1) {
        uu += __shfl_down_sync(0xffffffffu, uu, off);
        vv += __shfl_down_sync(0xffffffffu, vv, off);
    }
    if (c == 0) {
        g_uv[l * HEADS + h] = uu;
        g_uv[LL * HEADS + l * HEADS + h] = vv;
    }
}

__global__ void k_hist(const int* __restrict__ ei) {
    int e = blockIdx.x * blockDim.x + threadIdx.x;
    if (e >= Ee) return;
    atomicAdd(&g_deg[__ldg(&ei[Ee + e])], 1);
}

// ---------------- node encoder (fp16 h) ------------------------------------
__global__ void k_enc(const float* __restrict__ x, const float* __restrict__ ew,
                      const float* __restrict__ eb) {
    int i = blockIdx.x * blockDim.x + threadIdx.x;
    if (i >= Nn * HIDD) return;
    int n = i >> 7, c = i & 127;
    g_hh[i] = __float2half_rn(x[n] * ew[c] + eb[c]);
}

__global__ void k_scan1() {
    __shared__ int sd[256];
    int t = threadIdx.x;
    int i = blockIdx.x * 256 + t;
    int v = (i < Nn) ? g_deg[i] : 0;
    sd[t] = v;
    __syncthreads();
    for (int off = 1; off < 256; off <<= 1) {
        int x = (t >= off) ? sd[t - off] : 0;
        __syncthreads();
        sd[t] += x;
        __syncthreads();
    }
    if (i < Nn) g_row[i] = sd[t] - v;          // exclusive within chunk
    if (t == 255) g_bsum[blockIdx.x] = sd[255];
}

// parallel exclusive scan over NCHUNK block sums (single 512-thread block)
__global__ void k_scan2() {
    __shared__ int sd[512];
    int t = threadIdx.x;
    int v = (t < NCHUNK) ? g_bsum[t] : 0;
    sd[t] = v;
    __syncthreads();
    for (int off = 1; off < 512; off <<= 1) {
        int x = (t >= off) ? sd[t - off] : 0;
        __syncthreads();
        sd[t] += x;
        __syncthreads();
    }
    if (t < NCHUNK) g_boff[t] = sd[t] - v;     // exclusive
}

__global__ void k_scan3() {
    int i = blockIdx.x * blockDim.x + threadIdx.x;
    if (i == 0) g_row[Nn] = Ee;
    if (i < GG * HIDD) g_pooled[i] = 0.f;
    if (i < GG) g_cnt[i] = 0.f;
    if (i >= Nn) return;
    int r = g_row[i] + g_boff[i >> 8];
    g_row[i] = r;
    g_cur[i] = r;
}

__global__ void k_scatter(const int* __restrict__ ei, const float* __restrict__ ea) {
    int e = blockIdx.x * blockDim.x + threadIdx.x;
    if (e >= Ee) return;
    int d = __ldg(&ei[Ee + e]);
    int pos = atomicAdd(&g_cur[d], 1);
    g_pack[pos] = make_int2(__ldg(&ei[e]), __float_as_int(__ldg(&ea[e])));
}

// ------- xs = h @ W via fp16 m16n8k16 mma + ldmatrix; 128x64 tile ----------
__global__ void __launch_bounds__(256) k_gemm(const unsigned* __restrict__ wt,
                      const float* __restrict__ att_src,
                      const float* __restrict__ att_dst, int l) {
    __shared__ __align__(16) unsigned As2[128 * 64];  // 32 KB
    __shared__ __align__(16) unsigned Wt2[64 * 64];   // 16 KB
    int tid = threadIdx.x;
    int warp = tid >> 5, lane = tid & 31;
    int g = lane >> 2, t = lane & 3;
    int br = blockIdx.x * 128;
    int y = blockIdx.y;               // N-half: cols y*64 .. y*64+63
    int r0 = warp * 16 + g;

#pragma unroll
    for (int q = 0; q < 8; q++) {
        int idx = tid + q * 256;
        int row = idx >> 4, f4 = idx & 15;
        int gr = br + row;
        float4 v = make_float4(0.f, 0.f, 0.f, 0.f);
        if (gr < Nn) v = *(const float4*)&g_hh[gr * HIDD + f4 * 8];
        *(float4*)&As2[row * 64 + ((f4 * 4) ^ ((row & 7) << 2))] = v;
    }
    const float4* wsrc = (const float4*)(wt + (l * 2 + y) * 4096);
#pragma unroll
    for (int q = 0; q < 4; q++) {
        int idx = tid + q * 256;
        *(float4*)&Wt2[idx * 4] = wsrc[idx];
    }
    __syncthreads();

    float acc[8][4];
#pragma unroll
    for (int nt = 0; nt < 8; nt++) { acc[nt][0]=acc[nt][1]=acc[nt][2]=acc[nt][3]=0.f; }

    unsigned asBase = smem_u32(As2);
    unsigned wtBase = smem_u32(Wt2);
    int rowA = warp * 16 + ((lane >> 3) & 1) * 8 + (lane & 7);
    int bA   = (lane >> 4) * 4;            // 0 or 4 (hi chunk)
    int swA  = (rowA & 7) << 2;
    unsigned aRow = asBase + rowA * 64 * 4;
    int colLo = lane & 7;
    int bB    = ((lane >> 3) & 1) * 4;
    int colSel = (lane >> 4) & 1;
    int swB   = colLo << 2;
    unsigned bRow[4];
#pragma unroll
    for (int p = 0; p < 4; p++)
        bRow[p] = wtBase + ((2 * p + colSel) * 8 + colLo) * 64 * 4;

#pragma unroll
    for (int s = 0; s < 8; s++) {
        unsigned a0, a1, a2, a3;
        unsigned aAddr = aRow + (((8 * s + bA) ^ swA) << 2);
        asm volatile("ldmatrix.sync.aligned.m8n8.x4.shared.b16 {%0,%1,%2,%3}, [%4];"
                     : "=r"(a0), "=r"(a1), "=r"(a2), "=r"(a3) : "r"(aAddr));
        unsigned bOff = ((8 * s + bB) ^ swB) << 2;
#pragma unroll
        for (int p = 0; p < 4; p++) {
            unsigned b0, b1, b2, b3;
            asm volatile("ldmatrix.sync.aligned.m8n8.x4.shared.b16 {%0,%1,%2,%3}, [%4];"
                         : "=r"(b0), "=r"(b1), "=r"(b2), "=r"(b3)
                         : "r"(bRow[p] + bOff));
            int ntA = 2 * p, ntB = 2 * p + 1;
            asm volatile(
                "mma.sync.aligned.m16n8k16.row.col.f32.f16.f16.f32 "
                "{%0,%1,%2,%3}, {%4,%5,%6,%7}, {%8,%9}, {%0,%1,%2,%3};"
                : "+f"(acc[ntA][0]), "+f"(acc[ntA][1]), "+f"(acc[ntA][2]), "+f"(acc[ntA][3])
                : "r"(a0), "r"(a1), "r"(a2), "r"(a3), "r"(b0), "r"(b1));
            asm volatile(
                "mma.sync.aligned.m16n8k16.row.col.f32.f16.f16.f32 "
                "{%0,%1,%2,%3}, {%4,%5,%6,%7}, {%8,%9}, {%0,%1,%2,%3};"
                : "+f"(acc[ntB][0]), "+f"(acc[ntB][1]), "+f"(acc[ntB][2]), "+f"(acc[ntB][3])
                : "r"(a0), "r"(a1), "r"(a2), "r"(a3), "r"(b2), "r"(b3));
        }
    }

    int gr0 = br + r0, gr1 = br + r0 + 8;
#pragma unroll
    for (int nt = 0; nt < 8; nt++) {
        int c = y * 64 + nt * 8 + 2 * t;
        if (gr0 < Nn)
            *(__half2*)&g_xsh[gr0 * HIDD + c] = __floats2half2_rn(acc[nt][0], acc[nt][1]);
        if (gr1 < Nn)
            *(__half2*)&g_xsh[gr1 * HIDD + c] = __floats2half2_rn(acc[nt][2], acc[nt][3]);
    }

#pragma unroll
    for (int hh = 0; hh < 2; hh++) {
        float ps0 = 0.f, pd0 = 0.f, ps1 = 0.f, pd1 = 0.f;
#pragma unroll
        for (int j = 0; j < 4; j++) {
            int nt = hh * 4 + j;
            int c0 = l * HIDD + y * 64 + nt * 8 + 2 * t;
            float s0 = att_src[c0], s1 = att_src[c0 + 1];
            float d0 = att_dst[c0], d1 = att_dst[c0 + 1];
            ps0 += acc[nt][0] * s0 + acc[nt][1] * s1;
            ps1 += acc[nt][2] * s0 + acc[nt][3] * s1;
            pd0 += acc[nt][0] * d0 + acc[nt][1] * d1;
            pd1 += acc[nt][2] * d0 + acc[nt][3] * d1;
        }
        ps0 += __shfl_down_sync(0xffffffffu, ps0, 2, 4);
        ps0 += __shfl_down_sync(0xffffffffu, ps0, 1, 4);
        ps1 += __shfl_down_sync(0xffffffffu, ps1, 2, 4);
        ps1 += __shfl_down_sync(0xffffffffu, ps1, 1, 4);
        pd0 += __shfl_down_sync(0xffffffffu, pd0, 2, 4);
        pd0 += __shfl_down_sync(0xffffffffu, pd0, 1, 4);
        pd1 += __shfl_down_sync(0xffffffffu, pd1, 2, 4);
        pd1 += __shfl_down_sync(0xffffffffu, pd1, 1, 4);
        if (t == 0) {
            int gh = y * 2 + hh;
            if (gr0 < Nn) { g_as[gr0 * HEADS + gh] = ps0; g_ad[gr0 * HEADS + gh] = pd0; }
            if (gr1 < Nn) { g_as[gr1 * HEADS + gh] = ps1; g_ad[gr1 * HEADS + gh] = pd1; }
        }
    }
}

// ------- fused edge kernel (R13 form): warp per dst, 4-wide ----------------
__global__ void __launch_bounds__(64) k_edge(
        const int2* __restrict__ pack, const float* __restrict__ asv_p,
        const __half* __restrict__ xs, const int* __restrict__ rowp,
        const float* __restrict__ conv_b,
        const float* __restrict__ gamma, const float* __restrict__ beta,
        const float* __restrict__ mean, const float* __restrict__ var,
        int l) {
    int warp = (blockIdx.x * blockDim.x + threadIdx.x) >> 5;
    int lane = threadIdx.x & 31;
    if (warp >= Nn) return;
    const int d = warp;
    const int h = lane >> 3;
    const int r0 = __ldg(&rowp[d]), r1 = __ldg(&rowp[d + 1]);
    const float base = g_ad[d * HEADS + h] + g_uv[LL * HEADS + l * HEADS + h];
    const float u = g_uv[l * HEADS + h];

    float den = 0.f;
    float ac0 = 0.f, ac1 = 0.f, ac2 = 0.f, ac3 = 0.f;

    int e = r0;
    for (; e + 3 < r1; e += 4) {
        int2 P0 = __ldg(&pack[e]);
        int2 P1 = __ldg(&pack[e + 1]);
        int2 P2 = __ldg(&pack[e + 2]);
        int2 P3 = __ldg(&pack[e + 3]);
        float as0 = __ldg(&asv_p[P0.x * HEADS + h]);
        float as1 = __ldg(&asv_p[P1.x * HEADS + h]);
        float as2 = __ldg(&asv_p[P2.x * HEADS + h]);
        float as3 = __ldg(&asv_p[P3.x * HEADS + h]);
        uint2 X0 = __ldg((const uint2*)&xs[P0.x * HIDD + lane * 4]);
        uint2 X1 = __ldg((const uint2*)&xs[P1.x * HIDD + lane * 4]);
        uint2 X2 = __ldg((const uint2*)&xs[P2.x * HIDD + lane * 4]);
        uint2 X3 = __ldg((const uint2*)&xs[P3.x * HIDD + lane * 4]);
        float al0 = as0 + base + __int_as_float(P0.y) * u;
        float al1 = as1 + base + __int_as_float(P1.y) * u;
        float al2 = as2 + base + __int_as_float(P2.y) * u;
        float al3 = as3 + base + __int_as_float(P3.y) * u;
        al0 = (al0 > 0.f) ? al0 : 0.2f * al0;
        al1 = (al1 > 0.f) ? al1 : 0.2f * al1;
        al2 = (al2 > 0.f) ? al2 : 0.2f * al2;
        al3 = (al3 > 0.f) ? al3 : 0.2f * al3;
        float p0 = __expf(al0);
        float p1 = __expf(al1);
        float p2 = __expf(al2);
        float p3 = __expf(al3);
        den += (p0 + p1) + (p2 + p3);
        float2 A0 = __half22float2(*(__half2*)&X0.x), B0 = __half22float2(*(__half2*)&X0.y);
        float2 A1 = __half22float2(*(__half2*)&X1.x), B1 = __half22float2(*(__half2*)&X1.y);
        float2 A2 = __half22float2(*(__half2*)&X2.x), B2 = __half22float2(*(__half2*)&X2.y);
        float2 A3 = __half22float2(*(__half2*)&X3.x), B3 = __half22float2(*(__half2*)&X3.y);
        ac0 += p0 * A0.x + p1 * A1.x + p2 * A2.x + p3 * A3.x;
        ac1 += p0 * A0.y + p1 * A1.y + p2 * A2.y + p3 * A3.y;
        ac2 += p0 * B0.x + p1 * B1.x + p2 * B2.x + p3 * B3.x;
        ac3 += p0 * B0.y + p1 * B1.y + p2 * B2.y + p3 * B3.y;
    }
    for (; e < r1; e++) {
        int2 P0 = __ldg(&pack[e]);
        float as0 = __ldg(&asv_p[P0.x * HEADS + h]);
        uint2 X0 = __ldg((const uint2*)&xs[P0.x * HIDD + lane * 4]);
        float al0 = as0 + base + __int_as_float(P0.y) * u;
        al0 = (al0 > 0.f) ? al0 : 0.2f * al0;
        float p0 = __expf(al0);
        den += p0;
        float2 A0 = __half22float2(*(__half2*)&X0.x), B0 = __half22float2(*(__half2*)&X0.y);
        ac0 += p0 * A0.x;
        ac1 += p0 * A0.y;
        ac2 += p0 * B0.x;
        ac3 += p0 * B0.y;
    }
    float scale = 1.f / (den + 1e-16f);

    int cb = l * HIDD + lane * 4;
    float4 cb4 = *(const float4*)&conv_b[cb];
    float4 gm4 = *(const float4*)&gamma[cb];
    float4 bt4 = *(const float4*)&beta[cb];
    float4 mn4 = *(const float4*)&mean[cb];
    float4 vr4 = *(const float4*)&var[cb];
    uint2 H = *(const uint2*)&g_hh[d * HIDD + lane * 4];
    float2 h01 = __half22float2(*(__half2*)&H.x);
    float2 h23 = __half22float2(*(__half2*)&H.y);
    float o0 = (ac0 * scale + cb4.x - mn4.x) * rsqrtf(vr4.x + 1e-5f) * gm4.x + bt4.x;
    float o1 = (ac1 * scale + cb4.y - mn4.y) * rsqrtf(vr4.y + 1e-5f) * gm4.y + bt4.y;
    float o2 = (ac2 * scale + cb4.z - mn4.z) * rsqrtf(vr4.z + 1e-5f) * gm4.z + bt4.z;
    float o3 = (ac3 * scale + cb4.w - mn4.w) * rsqrtf(vr4.w + 1e-5f) * gm4.w + bt4.w;
    h01.x += fmaxf(o0, 0.f);
    h01.y += fmaxf(o1, 0.f);
    h23.x += fmaxf(o2, 0.f);
    h23.y += fmaxf(o3, 0.f);
    __half2 q0 = __floats2half2_rn(h01.x, h01.y);
    __half2 q1 = __floats2half2_rn(h23.x, h23.y);
    *(uint2*)&g_hh[d * HIDD + lane * 4] = make_uint2(*(unsigned*)&q0, *(unsigned*)&q1);
}

// ---------------- pooling ---------------------------------------------------
#define NPB 256
__global__ void k_pool(const int* __restrict__ batch) {
    int c = threadIdx.x;              // 128 channels
    int n0 = blockIdx.x * NPB;
    int n1 = min(n0 + NPB, Nn);
    int cur = -1; float s = 0.f; float cn = 0.f;
    for (int n = n0; n < n1; n++) {
        int g = batch[n];
        if (g != cur) {
            if (cur >= 0) {
                atomicAdd(&g_pooled[cur * HIDD + c], s);
                if (c == 0) atomicAdd(&g_cnt[cur], cn);
            }
            cur = g; s = 0.f; cn = 0.f;
        }
        s += __half2float(g_hh[n * HIDD + c]);
        cn += 1.f;
    }
    if (cur >= 0) {
        atomicAdd(&g_pooled[cur * HIDD + c], s);
        if (c == 0) atomicAdd(&g_cnt[cur], cn);
    }
}

// ---------------- classifier head (single block) ---------------------------
__global__ void __launch_bounds__(512) k_mlp(const float* __restrict__ w1,
                      const float* __restrict__ b1,
                      const float* __restrict__ w2, const float* __restrict__ b2,
                      float* __restrict__ out) {
    __shared__ float z[GG * 64];
    int t = threadIdx.x;
    for (int i = t; i < GG * 64; i += 512) {
        int g = i >> 6, j = i & 63;
        float cnt = fmaxf(g_cnt[g], 1.f);
        float s = 0.f;
        for (int k = 0; k < HIDD; k++) s += g_pooled[g * HIDD + k] * w1[k * 64 + j];
        z[i] = fmaxf(s / cnt + b1[j], 0.f);
    }
    __syncthreads();
    if (t < GG) {
        float s = b2[0];
        for (int j = 0; j < 64; j++) s += z[t * 64 + j] * w2[j];
        out[t] = 1.f / (1.f + __expf(-s));
    }
}

// ---------------- launch ----------------------------------------------------
extern "C" void kernel_launch(void* const* d_in, const int* in_sizes, int n_in,
                              void* d_out, int out_size) {
    const float* x        = (const float*)d_in[0];
    const float* ea       = (const float*)d_in[1];
    const int*   ei       = (const int*)  d_in[2];
    const int*   batch    = (const int*)  d_in[3];
    const float* enc_w    = (const float*)d_in[4];
    const float* enc_b    = (const float*)d_in[5];
    const float* eenc_w   = (const float*)d_in[6];
    const float* eenc_b   = (const float*)d_in[7];
    const float* lin_w    = (const float*)d_in[8];
    const float* att_src  = (const float*)d_in[9];
    const float* att_dst  = (const float*)d_in[10];
    const float* att_edge = (const float*)d_in[11];
    const float* lin_ew   = (const float*)d_in[12];
    const float* conv_b   = (const float*)d_in[13];
    const float* bn_gamma = (const float*)d_in[14];
    const float* bn_beta  = (const float*)d_in[15];
    const float* bn_mean  = (const float*)d_in[16];
    const float* bn_var   = (const float*)d_in[17];
    const float* w1       = (const float*)d_in[18];
    const float* b1       = (const float*)d_in[19];
    const float* w2       = (const float*)d_in[20];
    const float* b2       = (const float*)d_in[21];
    float* out = (float*)d_out;

    unsigned* wt = nullptr;
    cudaGetSymbolAddress((void**)&wt, g_wt);
    int2* packp = nullptr;
    cudaGetSymbolAddress((void**)&packp, g_pack);
    float* asp = nullptr;
    cudaGetSymbolAddress((void**)&asp, g_as);
    __half* xsp = nullptr;
    cudaGetSymbolAddress((void**)&xsp, g_xsh);
    int* rowp = nullptr;
    cudaGetSymbolAddress((void**)&rowp, g_row);

    const int TB = 256;
    int gridNH = (Nn * HIDD + TB - 1) / TB;
    int gridE  = (Ee + TB - 1) / TB;
    int gridN  = (Nn + TB - 1) / TB;
    int gridNW2 = (Nn * 32 + 63) / 64;
    dim3 ggrid((Nn + 127) / 128, 2);

    k_uv<<<NCHUNK, 256>>>(eenc_w, eenc_b, lin_ew, att_edge, lin_w);  // +zero deg +W prep
    k_hist<<<gridE, TB>>>(ei);
    k_enc<<<gridNH, TB>>>(x, enc_w, enc_b);
    k_gemm<<<ggrid, 256>>>(wt, att_src, att_dst, 0);
    k_scan1<<<NCHUNK, 256>>>();
    k_scan2<<<1, 512>>>();
    k_scan3<<<gridN, TB>>>();
    k_scatter<<<gridE, TB>>>(ei, ea);

    k_edge<<<gridNW2, 64>>>(packp, asp, xsp, rowp,
                            conv_b, bn_gamma, bn_beta, bn_mean, bn_var, 0);
    k_gemm<<<ggrid, 256>>>(wt, att_src, att_dst, 1);
    k_edge<<<gridNW2, 64>>>(packp, asp, xsp, rowp,
                            conv_b, bn_gamma, bn_beta, bn_mean, bn_var, 1);

    k_pool<<<(Nn + NPB - 1) / NPB, 128>>>(batch);
    k_mlp<<<1, 512>>>(w1, b1, w2, b2, out);
}

// round 16
// speedup vs baseline: 1.0756x; 1.0756x over previous
#include <cuda_runtime.h>
#include <cuda_fp16.h>

#define Nn   100000
#define Ee   1600000
#define HIDD 128
#define HEADS 4
#define CH   32
#define LL   2
#define GG   64
#define NCHUNK ((Nn + 255) / 256)   // 391

// ---------------- scratch (static device globals; no allocation) -----------
__device__ __align__(16) __half   g_hh[Nn*HIDD];    // h (fp16, sole copy)
__device__ __align__(16) __half   g_xsh[Nn*HIDD];   // fp16 xs (consumer: k_edge)
__device__ __align__(16) float    g_as[Nn*HEADS];
__device__ __align__(16) float    g_ad[Nn*HEADS];
__device__ __align__(16) float    g_uv[2*LL*HEADS];
__device__ __align__(16) float    g_pooled[GG*HIDD];
__device__           float        g_cnt[GG];
__device__ __align__(16) float    g_z[GG*64];
__device__ __align__(16) unsigned g_wt[2*2*64*64];  // W fp16, transposed+swizzled
// CSR by destination
__device__ __align__(16) int      g_deg[Nn];
__device__ __align__(16) int      g_row[Nn + 1];
__device__ __align__(16) int      g_cur[Nn];
__device__ __align__(16) int      g_bsum[NCHUNK];
__device__ __align__(16) int      g_boff[NCHUNK];
__device__ __align__(16) int2     g_pack[Ee];      // (src, ea bits)

__device__ __forceinline__ unsigned smem_u32(const void* p) {
    unsigned a;
    asm("{ .reg .u64 t; cvta.to.shared.u64 t, %1; cvt.u32.u64 %0, t; }"
        : "=r"(a) : "l"(p));
    return a;
}

// ---- block 0: uv precompute; blocks 1-4: W fp16 transpose; all: zero deg --
__global__ void k_uv(const float* __restrict__ eenc_w, const float* __restrict__ eenc_b,
                     const float* __restrict__ lew, const float* __restrict__ att_e,
                     const float* __restrict__ lin_w) {
    int i = blockIdx.x * blockDim.x + threadIdx.x;
    if (i < Nn) g_deg[i] = 0;
    if (blockIdx.x >= 1 && blockIdx.x <= 4) {
        int li = (blockIdx.x - 1) >> 1, yy = (blockIdx.x - 1) & 1;
        const float* W = lin_w + li * HIDD * HIDD;
#pragma unroll
        for (int q = 0; q < 16; q++) {
            int idx = threadIdx.x + q * 256;   // 0..4095
            int hk = idx >> 6, col = idx & 63;
            float w0 = W[(2 * hk) * HIDD + yy * 64 + col];
            float w1 = W[(2 * hk + 1) * HIDD + yy * 64 + col];
            __half2 v = __floats2half2_rn(w0, w1);
            g_wt[((li * 2 + yy) * 64 + col) * 64 + (hk ^ ((col & 7) << 2))] =
                *(unsigned*)&v;
        }
        return;
    }
    if (blockIdx.x != 0) return;
    int tid = threadIdx.x;                 // 256 = L*H*C
    int l = tid >> 7, h = (tid >> 5) & 3, c = tid & 31;
    const float* W = lew + l * HIDD * HIDD;
    int col = h * CH + c;
    float wc = 0.f, bc = 0.f;
    for (int k = 0; k < HIDD; k++) {
        float w = W[k * HIDD + col];
        wc += eenc_w[k] * w;
        bc += eenc_b[k] * w;
    }
    float ae = att_e[l * HEADS * CH + h * CH + c];
    float uu = wc * ae, vv = bc * ae;
    for (int off = 16; off; off >>= 1) {
        uu += __shfl_down_sync(0xffffffffu, uu, off);
        vv += __shfl_down_sync(0xffffffffu, vv, off);
    }
    if (c == 0) {
        g_uv[l * HEADS + h] = uu;
        g_uv[LL * HEADS + l * HEADS + h] = vv;
    }
}

// ---------------- node encoder (fp16 h) + fused degree histogram -----------
__global__ void k_enc(const float* __restrict__ x, const float* __restrict__ ew,
                      const float* __restrict__ eb, const int* __restrict__ ei) {
    int i = blockIdx.x * blockDim.x + threadIdx.x;
    if (i < Ee) atomicAdd(&g_deg[__ldg(&ei[Ee + i])], 1);
    if (i >= Nn * HIDD) return;
    int n = i >> 7, c = i & 127;
    g_hh[i] = __float2half_rn(x[n] * ew[c] + eb[c]);
}

__global__ void k_scan1() {
    __shared__ int sd[256];
    int t = threadIdx.x;
    int i = blockIdx.x * 256 + t;
    int v = (i < Nn) ? g_deg[i] : 0;
    sd[t] = v;
    __syncthreads();
    for (int off = 1; off < 256; off <<= 1) {
        int x = (t >= off) ? sd[t - off] : 0;
        __syncthreads();
        sd[t] += x;
        __syncthreads();
    }
    if (i < Nn) g_row[i] = sd[t] - v;          // exclusive within chunk
    if (t == 255) g_bsum[blockIdx.x] = sd[255];
}

// parallel exclusive scan over NCHUNK block sums (single 512-thread block)
__global__ void k_scan2() {
    __shared__ int sd[512];
    int t = threadIdx.x;
    int v = (t < NCHUNK) ? g_bsum[t] : 0;
    sd[t] = v;
    __syncthreads();
    for (int off = 1; off < 512; off <<= 1) {
        int x = (t >= off) ? sd[t - off] : 0;
        __syncthreads();
        sd[t] += x;
        __syncthreads();
    }
    if (t < NCHUNK) g_boff[t] = sd[t] - v;     // exclusive
}

__global__ void k_scan3() {
    int i = blockIdx.x * blockDim.x + threadIdx.x;
    if (i == 0) g_row[Nn] = Ee;
    if (i < GG * HIDD) g_pooled[i] = 0.f;
    if (i < GG) g_cnt[i] = 0.f;
    if (i >= Nn) return;
    int r = g_row[i] + g_boff[i >> 8];
    g_row[i] = r;
    g_cur[i] = r;
}

__global__ void k_scatter(const int* __restrict__ ei, const float* __restrict__ ea) {
    int e = blockIdx.x * blockDim.x + threadIdx.x;
    if (e >= Ee) return;
    int d = __ldg(&ei[Ee + e]);
    int pos = atomicAdd(&g_cur[d], 1);
    g_pack[pos] = make_int2(__ldg(&ei[e]), __float_as_int(__ldg(&ea[e])));
}

// ------- xs = h @ W via fp16 m16n8k16 mma + ldmatrix; 128x64 tile ----------
__global__ void __launch_bounds__(256) k_gemm(const unsigned* __restrict__ wt,
                      const float* __restrict__ att_src,
                      const float* __restrict__ att_dst, int l) {
    __shared__ __align__(16) unsigned As2[128 * 64];  // 32 KB
    __shared__ __align__(16) unsigned Wt2[64 * 64];   // 16 KB
    int tid = threadIdx.x;
    int warp = tid >> 5, lane = tid & 31;
    int g = lane >> 2, t = lane & 3;
    int br = blockIdx.x * 128;
    int y = blockIdx.y;               // N-half: cols y*64 .. y*64+63
    int r0 = warp * 16 + g;

#pragma unroll
    for (int q = 0; q < 8; q++) {
        int idx = tid + q * 256;
        int row = idx >> 4, f4 = idx & 15;
        int gr = br + row;
        float4 v = make_float4(0.f, 0.f, 0.f, 0.f);
        if (gr < Nn) v = *(const float4*)&g_hh[gr * HIDD + f4 * 8];
        *(float4*)&As2[row * 64 + ((f4 * 4) ^ ((row & 7) << 2))] = v;
    }
    const float4* wsrc = (const float4*)(wt + (l * 2 + y) * 4096);
#pragma unroll
    for (int q = 0; q < 4; q++) {
        int idx = tid + q * 256;
        *(float4*)&Wt2[idx * 4] = wsrc[idx];
    }
    __syncthreads();

    float acc[8][4];
#pragma unroll
    for (int nt = 0; nt < 8; nt++) { acc[nt][0]=acc[nt][1]=acc[nt][2]=acc[nt][3]=0.f; }

    unsigned asBase = smem_u32(As2);
    unsigned wtBase = smem_u32(Wt2);
    int rowA = warp * 16 + ((lane >> 3) & 1) * 8 + (lane & 7);
    int bA   = (lane >> 4) * 4;            // 0 or 4 (hi chunk)
    int swA  = (rowA & 7) << 2;
    unsigned aRow = asBase + rowA * 64 * 4;
    int colLo = lane & 7;
    int bB    = ((lane >> 3) & 1) * 4;
    int colSel = (lane >> 4) & 1;
    int swB   = colLo << 2;
    unsigned bRow[4];
#pragma unroll
    for (int p = 0; p < 4; p++)
        bRow[p] = wtBase + ((2 * p + colSel) * 8 + colLo) * 64 * 4;

#pragma unroll
    for (int s = 0; s < 8; s++) {
        unsigned a0, a1, a2, a3;
        unsigned aAddr = aRow + (((8 * s + bA) ^ swA) << 2);
        asm volatile("ldmatrix.sync.aligned.m8n8.x4.shared.b16 {%0,%1,%2,%3}, [%4];"
                     : "=r"(a0), "=r"(a1), "=r"(a2), "=r"(a3) : "r"(aAddr));
        unsigned bOff = ((8 * s + bB) ^ swB) << 2;
#pragma unroll
        for (int p = 0; p < 4; p++) {
            unsigned b0, b1, b2, b3;
            asm volatile("ldmatrix.sync.aligned.m8n8.x4.shared.b16 {%0,%1,%2,%3}, [%4];"
                         : "=r"(b0), "=r"(b1), "=r"(b2), "=r"(b3)
                         : "r"(bRow[p] + bOff));
            int ntA = 2 * p, ntB = 2 * p + 1;
            asm volatile(
                "mma.sync.aligned.m16n8k16.row.col.f32.f16.f16.f32 "
                "{%0,%1,%2,%3}, {%4,%5,%6,%7}, {%8,%9}, {%0,%1,%2,%3};"
                : "+f"(acc[ntA][0]), "+f"(acc[ntA][1]), "+f"(acc[ntA][2]), "+f"(acc[ntA][3])
                : "r"(a0), "r"(a1), "r"(a2), "r"(a3), "r"(b0), "r"(b1));
            asm volatile(
                "mma.sync.aligned.m16n8k16.row.col.f32.f16.f16.f32 "
                "{%0,%1,%2,%3}, {%4,%5,%6,%7}, {%8,%9}, {%0,%1,%2,%3};"
                : "+f"(acc[ntB][0]), "+f"(acc[ntB][1]), "+f"(acc[ntB][2]), "+f"(acc[ntB][3])
                : "r"(a0), "r"(a1), "r"(a2), "r"(a3), "r"(b2), "r"(b3));
        }
    }

    int gr0 = br + r0, gr1 = br + r0 + 8;
#pragma unroll
    for (int nt = 0; nt < 8; nt++) {
        int c = y * 64 + nt * 8 + 2 * t;
        if (gr0 < Nn)
            *(__half2*)&g_xsh[gr0 * HIDD + c] = __floats2half2_rn(acc[nt][0], acc[nt][1]);
        if (gr1 < Nn)
            *(__half2*)&g_xsh[gr1 * HIDD + c] = __floats2half2_rn(acc[nt][2], acc[nt][3]);
    }

#pragma unroll
    for (int hh = 0; hh < 2; hh++) {
        float ps0 = 0.f, pd0 = 0.f, ps1 = 0.f, pd1 = 0.f;
#pragma unroll
        for (int j = 0; j < 4; j++) {
            int nt = hh * 4 + j;
            int c0 = l * HIDD + y * 64 + nt * 8 + 2 * t;
            float s0 = att_src[c0], s1 = att_src[c0 + 1];
            float d0 = att_dst[c0], d1 = att_dst[c0 + 1];
            ps0 += acc[nt][0] * s0 + acc[nt][1] * s1;
            ps1 += acc[nt][2] * s0 + acc[nt][3] * s1;
            pd0 += acc[nt][0] * d0 + acc[nt][1] * d1;
            pd1 += acc[nt][2] * d0 + acc[nt][3] * d1;
        }
        ps0 += __shfl_down_sync(0xffffffffu, ps0, 2, 4);
        ps0 += __shfl_down_sync(0xffffffffu, ps0, 1, 4);
        ps1 += __shfl_down_sync(0xffffffffu, ps1, 2, 4);
        ps1 += __shfl_down_sync(0xffffffffu, ps1, 1, 4);
        pd0 += __shfl_down_sync(0xffffffffu, pd0, 2, 4);
        pd0 += __shfl_down_sync(0xffffffffu, pd0, 1, 4);
        pd1 += __shfl_down_sync(0xffffffffu, pd1, 2, 4);
        pd1 += __shfl_down_sync(0xffffffffu, pd1, 1, 4);
        if (t == 0) {
            int gh = y * 2 + hh;
            if (gr0 < Nn) { g_as[gr0 * HEADS + gh] = ps0; g_ad[gr0 * HEADS + gh] = pd0; }
            if (gr1 < Nn) { g_as[gr1 * HEADS + gh] = ps1; g_ad[gr1 * HEADS + gh] = pd1; }
        }
    }
}

// ------- fused edge kernel (R13 form): warp per dst, 4-wide ----------------
__global__ void __launch_bounds__(64) k_edge(
        const int2* __restrict__ pack, const float* __restrict__ asv_p,
        const __half* __restrict__ xs, const int* __restrict__ rowp,
        const float* __restrict__ conv_b,
        const float* __restrict__ gamma, const float* __restrict__ beta,
        const float* __restrict__ mean, const float* __restrict__ var,
        int l) {
    int warp = (blockIdx.x * blockDim.x + threadIdx.x) >> 5;
    int lane = threadIdx.x & 31;
    if (warp >= Nn) return;
    const int d = warp;
    const int h = lane >> 3;
    const int r0 = __ldg(&rowp[d]), r1 = __ldg(&rowp[d + 1]);
    const float base = g_ad[d * HEADS + h] + g_uv[LL * HEADS + l * HEADS + h];
    const float u = g_uv[l * HEADS + h];

    float den = 0.f;
    float ac0 = 0.f, ac1 = 0.f, ac2 = 0.f, ac3 = 0.f;

    int e = r0;
    for (; e + 3 < r1; e += 4) {
        int2 P0 = __ldg(&pack[e]);
        int2 P1 = __ldg(&pack[e + 1]);
        int2 P2 = __ldg(&pack[e + 2]);
        int2 P3 = __ldg(&pack[e + 3]);
        float as0 = __ldg(&asv_p[P0.x * HEADS + h]);
        float as1 = __ldg(&asv_p[P1.x * HEADS + h]);
        float as2 = __ldg(&asv_p[P2.x * HEADS + h]);
        float as3 = __ldg(&asv_p[P3.x * HEADS + h]);
        uint2 X0 = __ldg((const uint2*)&xs[P0.x * HIDD + lane * 4]);
        uint2 X1 = __ldg((const uint2*)&xs[P1.x * HIDD + lane * 4]);
        uint2 X2 = __ldg((const uint2*)&xs[P2.x * HIDD + lane * 4]);
        uint2 X3 = __ldg((const uint2*)&xs[P3.x * HIDD + lane * 4]);
        float al0 = as0 + base + __int_as_float(P0.y) * u;
        float al1 = as1 + base + __int_as_float(P1.y) * u;
        float al2 = as2 + base + __int_as_float(P2.y) * u;
        float al3 = as3 + base + __int_as_float(P3.y) * u;
        al0 = (al0 > 0.f) ? al0 : 0.2f * al0;
        al1 = (al1 > 0.f) ? al1 : 0.2f * al1;
        al2 = (al2 > 0.f) ? al2 : 0.2f * al2;
        al3 = (al3 > 0.f) ? al3 : 0.2f * al3;
        float p0 = __expf(al0);
        float p1 = __expf(al1);
        float p2 = __expf(al2);
        float p3 = __expf(al3);
        den += (p0 + p1) + (p2 + p3);
        float2 A0 = __half22float2(*(__half2*)&X0.x), B0 = __half22float2(*(__half2*)&X0.y);
        float2 A1 = __half22float2(*(__half2*)&X1.x), B1 = __half22float2(*(__half2*)&X1.y);
        float2 A2 = __half22float2(*(__half2*)&X2.x), B2 = __half22float2(*(__half2*)&X2.y);
        float2 A3 = __half22float2(*(__half2*)&X3.x), B3 = __half22float2(*(__half2*)&X3.y);
        ac0 += p0 * A0.x + p1 * A1.x + p2 * A2.x + p3 * A3.x;
        ac1 += p0 * A0.y + p1 * A1.y + p2 * A2.y + p3 * A3.y;
        ac2 += p0 * B0.x + p1 * B1.x + p2 * B2.x + p3 * B3.x;
        ac3 += p0 * B0.y + p1 * B1.y + p2 * B2.y + p3 * B3.y;
    }
    for (; e < r1; e++) {
        int2 P0 = __ldg(&pack[e]);
        float as0 = __ldg(&asv_p[P0.x * HEADS + h]);
        uint2 X0 = __ldg((const uint2*)&xs[P0.x * HIDD + lane * 4]);
        float al0 = as0 + base + __int_as_float(P0.y) * u;
        al0 = (al0 > 0.f) ? al0 : 0.2f * al0;
        float p0 = __expf(al0);
        den += p0;
        float2 A0 = __half22float2(*(__half2*)&X0.x), B0 = __half22float2(*(__half2*)&X0.y);
        ac0 += p0 * A0.x;
        ac1 += p0 * A0.y;
        ac2 += p0 * B0.x;
        ac3 += p0 * B0.y;
    }
    float scale = 1.f / (den + 1e-16f);

    int cb = l * HIDD + lane * 4;
    float4 cb4 = *(const float4*)&conv_b[cb];
    float4 gm4 = *(const float4*)&gamma[cb];
    float4 bt4 = *(const float4*)&beta[cb];
    float4 mn4 = *(const float4*)&mean[cb];
    float4 vr4 = *(const float4*)&var[cb];
    uint2 H = *(const uint2*)&g_hh[d * HIDD + lane * 4];
    float2 h01 = __half22float2(*(__half2*)&H.x);
    float2 h23 = __half22float2(*(__half2*)&H.y);
    float o0 = (ac0 * scale + cb4.x - mn4.x) * rsqrtf(vr4.x + 1e-5f) * gm4.x + bt4.x;
    float o1 = (ac1 * scale + cb4.y - mn4.y) * rsqrtf(vr4.y + 1e-5f) * gm4.y + bt4.y;
    float o2 = (ac2 * scale + cb4.z - mn4.z) * rsqrtf(vr4.z + 1e-5f) * gm4.z + bt4.z;
    float o3 = (ac3 * scale + cb4.w - mn4.w) * rsqrtf(vr4.w + 1e-5f) * gm4.w + bt4.w;
    h01.x += fmaxf(o0, 0.f);
    h01.y += fmaxf(o1, 0.f);
    h23.x += fmaxf(o2, 0.f);
    h23.y += fmaxf(o3, 0.f);
    __half2 q0 = __floats2half2_rn(h01.x, h01.y);
    __half2 q1 = __floats2half2_rn(h23.x, h23.y);
    *(uint2*)&g_hh[d * HIDD + lane * 4] = make_uint2(*(unsigned*)&q0, *(unsigned*)&q1);
}

// ---------------- pooling ---------------------------------------------------
#define NPB 256
__global__ void k_pool(const int* __restrict__ batch) {
    int c = threadIdx.x;              // 128 channels
    int n0 = blockIdx.x * NPB;
    int n1 = min(n0 + NPB, Nn);
    int cur = -1; float s = 0.f; float cn = 0.f;
    for (int n = n0; n < n1; n++) {
        int g = batch[n];
        if (g != cur) {
            if (cur >= 0) {
                atomicAdd(&g_pooled[cur * HIDD + c], s);
                if (c == 0) atomicAdd(&g_cnt[cur], cn);
            }
            cur = g; s = 0.f; cn = 0.f;
        }
        s += __half2float(g_hh[n * HIDD + c]);
        cn += 1.f;
    }
    if (cur >= 0) {
        atomicAdd(&g_pooled[cur * HIDD + c], s);
        if (c == 0) atomicAdd(&g_cnt[cur], cn);
    }
}

// ---------------- classifier head (R13 form: two kernels) ------------------
__global__ void k_mlp1(const float* __restrict__ w1, const float* __restrict__ b1) {
    int i = blockIdx.x * blockDim.x + threadIdx.x;   // GG*64
    if (i >= GG * 64) return;
    int g = i >> 6, j = i & 63;
    float cnt = fmaxf(g_cnt[g], 1.f);
    float s = 0.f;
    for (int k = 0; k < HIDD; k++) s += g_pooled[g * HIDD + k] * w1[k * 64 + j];
    g_z[i] = fmaxf(s / cnt + b1[j], 0.f);
}

__global__ void k_mlp2(const float* __restrict__ w2, const float* __restrict__ b2,
                       float* __restrict__ out) {
    int g = threadIdx.x;
    if (g >= GG) return;
    float s = b2[0];
    for (int j = 0; j < 64; j++) s += g_z[g * 64 + j] * w2[j];
    out[g] = 1.f / (1.f + __expf(-s));
}

// ---------------- launch ----------------------------------------------------
extern "C" void kernel_launch(void* const* d_in, const int* in_sizes, int n_in,
                              void* d_out, int out_size) {
    const float* x        = (const float*)d_in[0];
    const float* ea       = (const float*)d_in[1];
    const int*   ei       = (const int*)  d_in[2];
    const int*   batch    = (const int*)  d_in[3];
    const float* enc_w    = (const float*)d_in[4];
    const float* enc_b    = (const float*)d_in[5];
    const float* eenc_w   = (const float*)d_in[6];
    const float* eenc_b   = (const float*)d_in[7];
    const float* lin_w    = (const float*)d_in[8];
    const float* att_src  = (const float*)d_in[9];
    const float* att_dst  = (const float*)d_in[10];
    const float* att_edge = (const float*)d_in[11];
    const float* lin_ew   = (const float*)d_in[12];
    const float* conv_b   = (const float*)d_in[13];
    const float* bn_gamma = (const float*)d_in[14];
    const float* bn_beta  = (const float*)d_in[15];
    const float* bn_mean  = (const float*)d_in[16];
    const float* bn_var   = (const float*)d_in[17];
    const float* w1       = (const float*)d_in[18];
    const float* b1       = (const float*)d_in[19];
    const float* w2       = (const float*)d_in[20];
    const float* b2       = (const float*)d_in[21];
    float* out = (float*)d_out;

    unsigned* wt = nullptr;
    cudaGetSymbolAddress((void**)&wt, g_wt);
    int2* packp = nullptr;
    cudaGetSymbolAddress((void**)&packp, g_pack);
    float* asp = nullptr;
    cudaGetSymbolAddress((void**)&asp, g_as);
    __half* xsp = nullptr;
    cudaGetSymbolAddress((void**)&xsp, g_xsh);
    int* rowp = nullptr;
    cudaGetSymbolAddress((void**)&rowp, g_row);

    const int TB = 256;
    int gridNH = (Nn * HIDD + TB - 1) / TB;
    int gridE  = (Ee + TB - 1) / TB;
    int gridN  = (Nn + TB - 1) / TB;
    int gridNW2 = (Nn * 32 + 63) / 64;
    dim3 ggrid((Nn + 127) / 128, 2);

    k_uv<<<NCHUNK, 256>>>(eenc_w, eenc_b, lin_ew, att_edge, lin_w);  // +zero deg +W prep
    k_enc<<<gridNH, TB>>>(x, enc_w, enc_b, ei);                      // +hist
    k_gemm<<<ggrid, 256>>>(wt, att_src, att_dst, 0);
    k_scan1<<<NCHUNK, 256>>>();
    k_scan2<<<1, 512>>>();
    k_scan3<<<gridN, TB>>>();
    k_scatter<<<gridE, TB>>>(ei, ea);

    k_edge<<<gridNW2, 64>>>(packp, asp, xsp, rowp,
                            conv_b, bn_gamma, bn_beta, bn_mean, bn_var, 0);
    k_gemm<<<ggrid, 256>>>(wt, att_src, att_dst, 1);
    k_edge<<<gridNW2, 64>>>(packp, asp, xsp, rowp,
                            conv_b, bn_gamma, bn_beta, bn_mean, bn_var, 1);

    k_pool<<<(Nn + NPB - 1) / NPB, 128>>>(batch);
    k_mlp1<<<(GG * 64 + TB - 1) / TB, TB>>>(w1, b1);
    k_mlp2<<<1, 64>>>(w2, b2, out);
}